// round 12
// baseline (speedup 1.0000x reference)
#include <cuda_runtime.h>

#define BATCH  32
#define NPROB  256
#define NT     128          // 4 warps
#define NWARP  4
#define INF_F  1e9f
#define ARR_CAP 1024
#define QCAP   (NPROB + ARR_CAP + 8)

// order-preserving float<->uint encoding (a<b <=> enc(a)<enc(b))
__device__ __forceinline__ unsigned ford(float f) {
    unsigned u = __float_as_uint(f);
    return (u & 0x80000000u) ? ~u : (u | 0x80000000u);
}
__device__ __forceinline__ float forddec(unsigned e) {
    unsigned b = (e & 0x80000000u) ? (e ^ 0x80000000u) : ~e;
    return __uint_as_float(b);
}
__device__ __forceinline__ float dist4(float4 P, float4 G) {
    float d0 = P.x - G.x, d1 = P.y - G.y, d2 = P.z - G.z, d3 = P.w - G.w;
    return sqrtf(d0 * d0 + d1 * d1 + d2 * d2 + d3 * d3);
}

__global__ void __launch_bounds__(NT, 1)
hungarian_jv(const float* __restrict__ pred,
             const float* __restrict__ gt,
             float* __restrict__ out,
             int write_totals)
{
    const int b    = blockIdx.x;
    const int t    = threadIdx.x;        // owns cols c0=2t+1, c1=2t+2 (1-based)
    const int w    = t >> 5;
    const int lane = t & 31;
    const int c0   = 2 * t + 1, c1 = 2 * t + 2;

    __shared__ float4 pred_sh[NPROB];
    __shared__ float  u_sh[NPROB + 1];
    __shared__ int    p_sh[NPROB + 1];      // p[j]=row matched to col j (1-based), 0=free
    __shared__ int    way_sh[NPROB + 1];
    __shared__ float  up_sh[NPROB + 1];     // u[p[j]], phase-static
    __shared__ float4 pp_sh[NPROB + 1];     // pred[p[j]-1], phase-static
    __shared__ volatile unsigned long long keyv[2][NWARP]; // lock-free SAP key slots
    __shared__ __align__(16) ulonglong2 arrk[NWARP];       // ARR {K1,K2} per warp
    __shared__ int    rowowner[NPROB];
    __shared__ int    freeq[QCAP];
    __shared__ int    head_sh, tail_sh;
    __shared__ float  wsum[NWARP];

    // ---- stage ----
    for (int k = t; k < NPROB; k += NT)
        pred_sh[k] = ((const float4*)pred)[(size_t)b * NPROB + k];
    float4 g0 = ((const float4*)gt)[(size_t)b * NPROB + 2 * t];
    float4 g1 = ((const float4*)gt)[(size_t)b * NPROB + 2 * t + 1];
    for (int k = t; k <= NPROB; k += NT) { u_sh[k] = 0.0f; p_sh[k] = 0; }
    for (int k = t; k < NPROB; k += NT) rowowner[k] = 0x7fffffff;
    if (t < 2 * NWARP) keyv[t >> 2][t & 3] = ~0ull;   // tag=63: never matches iter 0
    __syncthreads();

    // ---- column reduction (min over squared dists; sqrtf monotone) ----
    float msq0 = INF_F, msq1 = INF_F; int mr0 = 0, mr1 = 0;
    for (int r = 0; r < NPROB; r++) {
        const float4 P = pred_sh[r];
        float a0 = P.x - g0.x, a1 = P.y - g0.y, a2 = P.z - g0.z, a3 = P.w - g0.w;
        float s0 = a0 * a0 + a1 * a1 + a2 * a2 + a3 * a3;
        float b0 = P.x - g1.x, b1 = P.y - g1.y, b2 = P.z - g1.z, b3 = P.w - g1.w;
        float s1 = b0 * b0 + b1 * b1 + b2 * b2 + b3 * b3;
        if (s0 < msq0) { msq0 = s0; mr0 = r; }
        if (s1 < msq1) { msq1 = s1; mr1 = r; }
    }
    float v0 = sqrtf(msq0), v1 = sqrtf(msq1);
    atomicMin(&rowowner[mr0], 2 * t);
    atomicMin(&rowowner[mr1], 2 * t + 1);
    __syncthreads();
    if (rowowner[mr0] == 2 * t)     p_sh[c0] = mr0 + 1;
    if (rowowner[mr1] == 2 * t + 1) p_sh[c1] = mr1 + 1;
    __syncthreads();
    if (t == 0) {
        int n = 0;
        for (int r = 0; r < NPROB; r++)
            if (rowowner[r] == 0x7fffffff) freeq[n++] = r + 1;   // 1-based rows
        head_sh = 0; tail_sh = n;
    }
    __syncthreads();

    // ---- augmenting row reduction (JV ARR), unchanged from R8 ----
    int steps = 0;
    while (true) {
        const int head = head_sh, tail = tail_sh;
        if (head >= tail || steps >= ARR_CAP) break;
        steps++;
        const int i = freeq[head];
        const float4 P = pred_sh[i - 1];
        const float rc0 = dist4(P, g0) - v0;
        const float rc1 = dist4(P, g1) - v1;
        float lm1, lm2; int lc1, lc2;
        if (rc0 <= rc1) { lm1 = rc0; lc1 = c0; lm2 = rc1; lc2 = c1; }
        else            { lm1 = rc1; lc1 = c1; lm2 = rc0; lc2 = c0; }

        const unsigned e1  = ford(lm1);
        const unsigned m1  = __reduce_min_sync(0xffffffffu, e1);
        const unsigned cd1 = (e1 == m1) ? (unsigned)lc1 : 0xffffffffu;
        const unsigned j1w = __reduce_min_sync(0xffffffffu, cd1);
        const bool iown    = (e1 == m1) && ((unsigned)lc1 == j1w);
        const float contrib = iown ? lm2 : lm1;
        const int   ccol    = iown ? lc2 : lc1;
        const unsigned e2  = ford(contrib);
        const unsigned m2  = __reduce_min_sync(0xffffffffu, e2);
        const unsigned cd2 = (e2 == m2) ? (unsigned)ccol : 0xffffffffu;
        const unsigned j2w = __reduce_min_sync(0xffffffffu, cd2);
        if (lane == 0)
            arrk[w] = make_ulonglong2((((unsigned long long)m1) << 32) | j1w,
                                      (((unsigned long long)m2) << 32) | j2w);
        __syncthreads();

        const ulonglong2 a0 = arrk[0];
        const ulonglong2 a1 = arrk[1];
        const ulonglong2 a2 = arrk[2];
        const ulonglong2 a3 = arrk[3];
        unsigned long long K1[4] = {a0.x, a1.x, a2.x, a3.x};
        unsigned long long K2[4] = {a0.y, a1.y, a2.y, a3.y};
        unsigned long long gm1 = K1[0]; int wd = 0;
        #pragma unroll
        for (int q = 1; q < 4; q++) if (K1[q] < gm1) { gm1 = K1[q]; wd = q; }
        unsigned long long gm2 = 0xffffffffffffffffULL;
        #pragma unroll
        for (int q = 0; q < 4; q++) {
            unsigned long long cq = (q == wd) ? K2[q] : K1[q];
            if (cq < gm2) gm2 = cq;
        }
        const int   j1 = (int)(gm1 & 0xffffffffu);
        const float u1 = forddec((unsigned)(gm1 >> 32));
        const int   j2 = (int)(gm2 & 0xffffffffu);
        const float u2 = forddec((unsigned)(gm2 >> 32));

        const bool strict = (u1 < u2);
        if (strict) {
            if (j1 == c0)      v0 -= (u2 - u1);
            else if (j1 == c1) v1 -= (u2 - u1);
        }
        if (t == 0) {
            int jA = j1;
            if (!strict && p_sh[j1] != 0) jA = j2;
            const int i0 = p_sh[jA];
            p_sh[jA] = i;
            u_sh[i]  = u2;
            int nh = head + 1, nt2 = tail;
            if (i0 != 0) {
                if (strict) { nh = head; freeq[head] = i0; }
                else        { freeq[nt2++] = i0; }
            }
            head_sh = nh; tail_sh = nt2;
        }
        __syncthreads();
    }

    const int h0  = head_sh;
    const int t0q = tail_sh;

    // ---- SAP phases: R8 scheme, barrier-free inner loop (tagged key slots) ----
    // key: [ ford(minv) (32) | col (9) << 8 | freebit << 7 | 0 << 6 | tag (6) ]
    unsigned it = 0;                       // global iteration counter (tag source)
    const int o0 = (w + 1) & 3, o1 = (w + 2) & 3, o2 = (w + 3) & 3;

    for (int idx = h0; idx < t0q; idx++) {
        const int i = freeq[idx];

        // phase-static gather: pj in regs; up/pp broadcast arrays in smem
        const int pj0  = p_sh[c0];
        const int pj1c = p_sh[c1];
        up_sh[c0] = u_sh[pj0];  pp_sh[c0] = pred_sh[pj0  ? pj0  - 1 : 0];
        up_sh[c1] = u_sh[pj1c]; pp_sh[c1] = pred_sh[pj1c ? pj1c - 1 : 0];
        if (t == 0) { p_sh[0] = i; up_sh[0] = u_sh[i]; pp_sh[0] = pred_sh[i - 1]; }

        float minv0 = INF_F, minv1 = INF_F, Smark0 = 0.0f, Smark1 = 0.0f, S = 0.0f;
        unsigned usedm = 0;
        int j0 = 0, jfreecol;
        __syncthreads();

        while (true) {
            if (j0 == c0)      { usedm |= 1u; Smark0 = S; minv0 = INF_F; }
            else if (j0 == c1) { usedm |= 2u; Smark1 = S; minv1 = INF_F; }

            const float4 P  = pp_sh[j0];          // smem broadcast
            const float  uu = up_sh[j0];
            float cur0 = dist4(P, g0) - uu - v0; if (usedm & 1u) cur0 = INF_F;
            float cur1 = dist4(P, g1) - uu - v1; if (usedm & 2u) cur1 = INF_F;
            if (cur0 < minv0) { minv0 = cur0; way_sh[c0] = j0; }
            if (cur1 < minv1) { minv1 = cur1; way_sh[c1] = j0; }

            float lm; int lc; unsigned fb;
            if (minv0 <= minv1) { lm = minv0; lc = c0; fb = (pj0  == 0) ? 1u : 0u; }
            else                { lm = minv1; lc = c1; fb = (pj1c == 0) ? 1u : 0u; }

            const unsigned e  = ford(lm);
            const unsigned m  = __reduce_min_sync(0xffffffffu, e);
            const unsigned cd = (e == m) ? (((unsigned)lc << 2) | (fb << 1)) : 0xffffffffu;
            const unsigned jc = __reduce_min_sync(0xffffffffu, cd);   // (col<<2)|(fb<<1)
            const unsigned tag = it & 63u;
            const unsigned par = it & 1u;
            const unsigned long long myk =
                (((unsigned long long)m) << 32) | ((unsigned long long)jc << 6) | tag;
            if (lane == 0) keyv[par][w] = myk;    // single STS, no barrier

            // spin for the other 3 warps' keys of this iteration
            unsigned long long x0, x1, x2;
            while (true) {
                x0 = keyv[par][o0]; x1 = keyv[par][o1]; x2 = keyv[par][o2];
                if (((x0 ^ tag) | (x1 ^ tag) | (x2 ^ tag) | 0ull) << 58 == 0ull) break;
            }
            unsigned long long bk = myk;
            if (x0 < bk) bk = x0;
            if (x1 < bk) bk = x1;
            if (x2 < bk) bk = x2;
            const unsigned lo    = (unsigned)(bk & 0xffffffffu);
            const float    delta = forddec((unsigned)(bk >> 32));
            const int      j1    = (int)(lo >> 8);

            S += delta;
            minv0 -= delta; minv1 -= delta;
            it++;
            j0 = j1;
            if (lo & 0x80u) { jfreecol = j1; break; }   // freebit: reached free column
        }

        __syncthreads();   // make all way_sh writes visible before the walk
        if (t == 0) {
            int j = jfreecol;
            while (j) { const int jn = way_sh[j]; p_sh[j] = p_sh[jn]; j = jn; }
            u_sh[i] += S;
        }
        if (usedm & 1u) { const float d = S - Smark0; u_sh[pj0]  += d; v0 -= d; }
        if (usedm & 2u) { const float d = S - Smark1; u_sh[pj1c] += d; v1 -= d; }
        __syncthreads();
    }

    // ---- epilogue: col4row[p[c]-1] = c-1 ; per-batch total ----
    float s = 0.0f;
    {
        const int r0 = p_sh[c0] - 1;
        const int r1 = p_sh[c1] - 1;
        out[(size_t)b * NPROB + r0] = (float)(2 * t);
        out[(size_t)b * NPROB + r1] = (float)(2 * t + 1);
        if (write_totals)
            s = dist4(pred_sh[r0], g0) + dist4(pred_sh[r1], g1);
    }
    if (write_totals) {
        #pragma unroll
        for (int off = 16; off; off >>= 1)
            s += __shfl_xor_sync(0xffffffffu, s, off);
        if (lane == 0) wsum[w] = s;
        __syncthreads();
        if (t == 0) {
            float acc = 0.0f;
            #pragma unroll
            for (int q = 0; q < NWARP; q++) acc += wsum[q];
            out[(size_t)BATCH * NPROB + b] = acc;
        }
    }
}

extern "C" void kernel_launch(void* const* d_in, const int* in_sizes, int n_in,
                              void* d_out, int out_size)
{
    const float* pred = (const float*)d_in[0];
    const float* gt   = (const float*)d_in[1];
    float* out        = (float*)d_out;
    const int wt      = (out_size >= BATCH * NPROB + BATCH) ? 1 : 0;
    hungarian_jv<<<BATCH, NT>>>(pred, gt, out, wt);
}

// round 13
// speedup vs baseline: 1.9518x; 1.9518x over previous
#include <cuda_runtime.h>

#define BATCH  32
#define NPROB  256
#define NT     128          // 4 warps
#define NWARP  4
#define INF_F  1e9f
#define ARR_CAP 1024
#define QCAP   (NPROB + ARR_CAP + 8)

// order-preserving float<->uint encoding (a<b <=> enc(a)<enc(b))
__device__ __forceinline__ unsigned ford(float f) {
    unsigned u = __float_as_uint(f);
    return (u & 0x80000000u) ? ~u : (u | 0x80000000u);
}
__device__ __forceinline__ float forddec(unsigned e) {
    unsigned b = (e & 0x80000000u) ? (e ^ 0x80000000u) : ~e;
    return __uint_as_float(b);
}
__device__ __forceinline__ float dist4(float4 P, float4 G) {
    float d0 = P.x - G.x, d1 = P.y - G.y, d2 = P.z - G.z, d3 = P.w - G.w;
    return sqrtf(d0 * d0 + d1 * d1 + d2 * d2 + d3 * d3);
}

__global__ void __launch_bounds__(NT, 1)
hungarian_jv(const float* __restrict__ pred,
             const float* __restrict__ gt,
             float* __restrict__ out,
             int write_totals)
{
    const int b    = blockIdx.x;
    const int t    = threadIdx.x;        // owns cols c0=2t+1, c1=2t+2 (1-based)
    const int w    = t >> 5;
    const int lane = t & 31;
    const int c0   = 2 * t + 1, c1 = 2 * t + 2;

    __shared__ float4 pred_sh[NPROB];
    __shared__ float  u_sh[NPROB + 1];
    __shared__ int    p_sh[NPROB + 1];      // p[j]=row matched to col j (1-based), 0=free
    __shared__ int    way_sh[NPROB + 1];
    __shared__ float  up_sh[NPROB + 1];     // u[p[j]], phase-static
    __shared__ float4 pp_sh[NPROB + 1];     // pred[p[j]-1], phase-static
    __shared__ __align__(16) unsigned long long keyv[2][NWARP];  // SAP keys (dbl-buffered)
    __shared__ __align__(16) ulonglong2 arrk[NWARP];             // ARR {K1,K2} per warp
    __shared__ int    rowowner[NPROB];
    __shared__ int    freeq[QCAP];
    __shared__ int    head_sh, tail_sh;
    __shared__ float  wsum[NWARP];

    // ---- stage ----
    for (int k = t; k < NPROB; k += NT)
        pred_sh[k] = ((const float4*)pred)[(size_t)b * NPROB + k];
    float4 g0 = ((const float4*)gt)[(size_t)b * NPROB + 2 * t];
    float4 g1 = ((const float4*)gt)[(size_t)b * NPROB + 2 * t + 1];
    for (int k = t; k <= NPROB; k += NT) { u_sh[k] = 0.0f; p_sh[k] = 0; }
    for (int k = t; k < NPROB; k += NT) rowowner[k] = 0x7fffffff;
    __syncthreads();

    // ---- column reduction (min over squared dists; sqrtf monotone) ----
    float msq0 = INF_F, msq1 = INF_F; int mr0 = 0, mr1 = 0;
    for (int r = 0; r < NPROB; r++) {
        const float4 P = pred_sh[r];
        float a0 = P.x - g0.x, a1 = P.y - g0.y, a2 = P.z - g0.z, a3 = P.w - g0.w;
        float s0 = a0 * a0 + a1 * a1 + a2 * a2 + a3 * a3;
        float b0 = P.x - g1.x, b1 = P.y - g1.y, b2 = P.z - g1.z, b3 = P.w - g1.w;
        float s1 = b0 * b0 + b1 * b1 + b2 * b2 + b3 * b3;
        if (s0 < msq0) { msq0 = s0; mr0 = r; }
        if (s1 < msq1) { msq1 = s1; mr1 = r; }
    }
    float v0 = sqrtf(msq0), v1 = sqrtf(msq1);
    atomicMin(&rowowner[mr0], 2 * t);
    atomicMin(&rowowner[mr1], 2 * t + 1);
    __syncthreads();
    if (rowowner[mr0] == 2 * t)     p_sh[c0] = mr0 + 1;
    if (rowowner[mr1] == 2 * t + 1) p_sh[c1] = mr1 + 1;
    __syncthreads();
    if (t == 0) {
        int n = 0;
        for (int r = 0; r < NPROB; r++)
            if (rowowner[r] == 0x7fffffff) freeq[n++] = r + 1;   // 1-based rows
        head_sh = 0; tail_sh = n;
    }
    __syncthreads();

    // ---- augmenting row reduction (JV ARR), unchanged from R8 ----
    int steps = 0;
    while (true) {
        const int head = head_sh, tail = tail_sh;
        if (head >= tail || steps >= ARR_CAP) break;
        steps++;
        const int i = freeq[head];
        const float4 P = pred_sh[i - 1];
        const float rc0 = dist4(P, g0) - v0;
        const float rc1 = dist4(P, g1) - v1;
        float lm1, lm2; int lc1, lc2;
        if (rc0 <= rc1) { lm1 = rc0; lc1 = c0; lm2 = rc1; lc2 = c1; }
        else            { lm1 = rc1; lc1 = c1; lm2 = rc0; lc2 = c0; }

        const unsigned e1  = ford(lm1);
        const unsigned m1  = __reduce_min_sync(0xffffffffu, e1);
        const unsigned cd1 = (e1 == m1) ? (unsigned)lc1 : 0xffffffffu;
        const unsigned j1w = __reduce_min_sync(0xffffffffu, cd1);
        const bool iown    = (e1 == m1) && ((unsigned)lc1 == j1w);
        const float contrib = iown ? lm2 : lm1;
        const int   ccol    = iown ? lc2 : lc1;
        const unsigned e2  = ford(contrib);
        const unsigned m2  = __reduce_min_sync(0xffffffffu, e2);
        const unsigned cd2 = (e2 == m2) ? (unsigned)ccol : 0xffffffffu;
        const unsigned j2w = __reduce_min_sync(0xffffffffu, cd2);
        if (lane == 0)
            arrk[w] = make_ulonglong2((((unsigned long long)m1) << 32) | j1w,
                                      (((unsigned long long)m2) << 32) | j2w);
        __syncthreads();

        const ulonglong2 a0 = arrk[0];
        const ulonglong2 a1 = arrk[1];
        const ulonglong2 a2 = arrk[2];
        const ulonglong2 a3 = arrk[3];
        unsigned long long K1[4] = {a0.x, a1.x, a2.x, a3.x};
        unsigned long long K2[4] = {a0.y, a1.y, a2.y, a3.y};
        unsigned long long gm1 = K1[0]; int wd = 0;
        #pragma unroll
        for (int q = 1; q < 4; q++) if (K1[q] < gm1) { gm1 = K1[q]; wd = q; }
        unsigned long long gm2 = 0xffffffffffffffffULL;
        #pragma unroll
        for (int q = 0; q < 4; q++) {
            unsigned long long cq = (q == wd) ? K2[q] : K1[q];
            if (cq < gm2) gm2 = cq;
        }
        const int   j1 = (int)(gm1 & 0xffffffffu);
        const float u1 = forddec((unsigned)(gm1 >> 32));
        const int   j2 = (int)(gm2 & 0xffffffffu);
        const float u2 = forddec((unsigned)(gm2 >> 32));

        const bool strict = (u1 < u2);
        if (strict) {
            if (j1 == c0)      v0 -= (u2 - u1);
            else if (j1 == c1) v1 -= (u2 - u1);
        }
        if (t == 0) {
            int jA = j1;
            if (!strict && p_sh[j1] != 0) jA = j2;
            const int i0 = p_sh[jA];
            p_sh[jA] = i;
            u_sh[i]  = u2;
            int nh = head + 1, nt2 = tail;
            if (i0 != 0) {
                if (strict) { nh = head; freeq[head] = i0; }
                else        { freeq[nt2++] = i0; }
            }
            head_sh = nh; tail_sh = nt2;
        }
        __syncthreads();
    }

    const int h0  = head_sh;
    const int t0q = tail_sh;

    // ---- SAP phases (R8 scheme; way in registers, flushed once per phase) ----
    for (int idx = h0; idx < t0q; idx++) {
        const int i = freeq[idx];

        // phase-static gather: pj in regs; up/pp broadcast arrays in smem
        const int pj0  = p_sh[c0];
        const int pj1c = p_sh[c1];
        up_sh[c0] = u_sh[pj0];  pp_sh[c0] = pred_sh[pj0  ? pj0  - 1 : 0];
        up_sh[c1] = u_sh[pj1c]; pp_sh[c1] = pred_sh[pj1c ? pj1c - 1 : 0];
        if (t == 0) { p_sh[0] = i; up_sh[0] = u_sh[i]; pp_sh[0] = pred_sh[i - 1]; }

        float minv0 = INF_F, minv1 = INF_F, Smark0 = 0.0f, Smark1 = 0.0f, S = 0.0f;
        int   way0 = 0, way1 = 0;          // register-resident back-pointers
        unsigned usedm = 0;
        int par = 0;
        int j0 = 0, jfreecol;
        __syncthreads();

        while (true) {
            if (j0 == c0)      { usedm |= 1u; Smark0 = S; minv0 = INF_F; }
            else if (j0 == c1) { usedm |= 2u; Smark1 = S; minv1 = INF_F; }

            const float4 P  = pp_sh[j0];          // smem broadcast
            const float  uu = up_sh[j0];
            float cur0 = dist4(P, g0) - uu - v0; if (usedm & 1u) cur0 = INF_F;
            float cur1 = dist4(P, g1) - uu - v1; if (usedm & 2u) cur1 = INF_F;
            if (cur0 < minv0) { minv0 = cur0; way0 = j0; }   // regs only
            if (cur1 < minv1) { minv1 = cur1; way1 = j0; }

            float lm; int lc; unsigned fb;
            if (minv0 <= minv1) { lm = minv0; lc = c0; fb = (pj0  == 0) ? 1u : 0u; }
            else                { lm = minv1; lc = c1; fb = (pj1c == 0) ? 1u : 0u; }

            const unsigned e  = ford(lm);
            const unsigned m  = __reduce_min_sync(0xffffffffu, e);
            const unsigned cd = (e == m) ? (((unsigned)lc << 1) | fb) : 0xffffffffu;
            const unsigned jc = __reduce_min_sync(0xffffffffu, cd);
            if (lane == 0)
                keyv[par][w] = (((unsigned long long)m) << 32) | jc;   // single STS pre-BAR
            __syncthreads();

            const ulonglong2 ka = *(const ulonglong2*)&keyv[par][0];
            const ulonglong2 kb = *(const ulonglong2*)&keyv[par][2];
            unsigned long long bk = ka.x;
            if (ka.y < bk) bk = ka.y;
            if (kb.x < bk) bk = kb.x;
            if (kb.y < bk) bk = kb.y;
            const unsigned lo    = (unsigned)(bk & 0xffffffffu);
            const int      j1    = (int)(lo >> 1);
            const float    delta = forddec((unsigned)(bk >> 32));

            S += delta;
            minv0 -= delta; minv1 -= delta;
            par ^= 1;
            j0 = j1;
            if (lo & 1u) { jfreecol = j1; break; }   // reached a free column
        }

        // flush back-pointers once, then walk
        way_sh[c0] = way0;
        way_sh[c1] = way1;
        __syncthreads();
        if (t == 0) {
            int j = jfreecol;
            while (j) { const int jn = way_sh[j]; p_sh[j] = p_sh[jn]; j = jn; }
            u_sh[i] += S;
        }
        if (usedm & 1u) { const float d = S - Smark0; u_sh[pj0]  += d; v0 -= d; }
        if (usedm & 2u) { const float d = S - Smark1; u_sh[pj1c] += d; v1 -= d; }
        __syncthreads();
    }

    // ---- epilogue: col4row[p[c]-1] = c-1 ; per-batch total ----
    float s = 0.0f;
    {
        const int r0 = p_sh[c0] - 1;
        const int r1 = p_sh[c1] - 1;
        out[(size_t)b * NPROB + r0] = (float)(2 * t);
        out[(size_t)b * NPROB + r1] = (float)(2 * t + 1);
        if (write_totals)
            s = dist4(pred_sh[r0], g0) + dist4(pred_sh[r1], g1);
    }
    if (write_totals) {
        #pragma unroll
        for (int off = 16; off; off >>= 1)
            s += __shfl_xor_sync(0xffffffffu, s, off);
        if (lane == 0) wsum[w] = s;
        __syncthreads();
        if (t == 0) {
            float acc = 0.0f;
            #pragma unroll
            for (int q = 0; q < NWARP; q++) acc += wsum[q];
            out[(size_t)BATCH * NPROB + b] = acc;
        }
    }
}

extern "C" void kernel_launch(void* const* d_in, const int* in_sizes, int n_in,
                              void* d_out, int out_size)
{
    const float* pred = (const float*)d_in[0];
    const float* gt   = (const float*)d_in[1];
    float* out        = (float*)d_out;
    const int wt      = (out_size >= BATCH * NPROB + BATCH) ? 1 : 0;
    hungarian_jv<<<BATCH, NT>>>(pred, gt, out, wt);
}